// round 16
// baseline (speedup 1.0000x reference)
#include <cuda_runtime.h>
#include <cuda_bf16.h>
#include <cstdint>

// Problem constants
#define IDIM   80
#define HDIM   512
#define WIN    160      // IN_EXTRA + IDIM
#define NSHIFT 81       // IN_EXTRA + 1
#define NTOK   2048     // B*T
#define KSEL   128      // 2*CDIM
#define TPB    8        // tokens per hcompute block

// packed f32x2 helpers (Blackwell sm_100a+)
#define FFMA2_ACC(acc, a, b) \
    asm("fma.rn.f32x2 %0, %1, %2, %0;" : "+l"(acc) : "l"(a), "l"(b))
#define ADD2(d, a, b) \
    asm("add.rn.f32x2 %0, %1, %2;" : "=l"(d) : "l"(a), "l"(b))
#define PACK2(d, lo, hi) \
    asm("mov.b64 %0, {%1, %2};" : "=l"(d) : "f"(lo), "f"(hi))
#define UNPACK2(lo, hi, v) \
    asm("mov.b64 {%0, %1}, %2;" : "=f"(lo), "=f"(hi) : "l"(v))

// ---------------- scratch (__device__ globals; no allocation) ----------------
__device__ float g_C[WIN * WIN];            // Gram matrix W_enc^T W_enc (160x160)
__device__ float g_v[WIN];                  // W_enc^T b_enc
__device__ unsigned long long g_packed[NTOK]; // (ordered(E)<<32)|q  via atomicMax
__device__ float g_WeT[WIN * HDIM];         // W_enc transposed
__device__ float g_WdT[HDIM * WIN];         // W_dec transposed
__device__ float g_h[NTOK * HDIM];          // masked h per token

// ---------------- K1: fused prep (gram + transposes + vb + zero) ----------------
// blocks 0..24: gram tile; 25..104: WeT; 105..184: WdT; 185..344: vb; 345: zero
__global__ __launch_bounds__(256) void prep_kernel(
    const float* __restrict__ W_enc, const float* __restrict__ b_enc,
    const float* __restrict__ W_dec)
{
    int blk = blockIdx.x;
    int tid = threadIdx.x;

    if (blk < 25) {
        __shared__ float SA[8][32];
        __shared__ float SB[8][32];
        int d0 = (blk % 5) * 32, e0 = (blk / 5) * 32;
        int dd = tid >> 5, ee = tid & 31;
        float a0 = 0.f, a1 = 0.f, a2 = 0.f, a3 = 0.f;
        for (int j0 = 0; j0 < HDIM; j0 += 8) {
            SA[dd][ee] = W_enc[(j0 + dd) * WIN + d0 + ee];
            SB[dd][ee] = W_enc[(j0 + dd) * WIN + e0 + ee];
            __syncthreads();
#pragma unroll
            for (int jj = 0; jj < 8; jj++) {
                float b = SB[jj][ee];
                a0 += SA[jj][dd] * b;
                a1 += SA[jj][dd + 8] * b;
                a2 += SA[jj][dd + 16] * b;
                a3 += SA[jj][dd + 24] * b;
            }
            __syncthreads();
        }
        g_C[(d0 + dd) * WIN + e0 + ee]      = a0;
        g_C[(d0 + dd + 8) * WIN + e0 + ee]  = a1;
        g_C[(d0 + dd + 16) * WIN + e0 + ee] = a2;
        g_C[(d0 + dd + 24) * WIN + e0 + ee] = a3;
    } else if (blk < 105) {
        __shared__ float tile[32][33];
        int bi = blk - 25;
        int bx = (bi % 5) * 32;
        int by = (bi / 5) * 32;
        int tx = tid & 31, ty = tid >> 5;
#pragma unroll
        for (int r = 0; r < 4; r++)
            tile[ty + 8 * r][tx] = W_enc[(by + ty + 8 * r) * WIN + bx + tx];
        __syncthreads();
#pragma unroll
        for (int r = 0; r < 4; r++)
            g_WeT[(bx + ty + 8 * r) * HDIM + by + tx] = tile[tx][ty + 8 * r];
    } else if (blk < 185) {
        __shared__ float tile[32][33];
        int bi = blk - 105;
        int bx = (bi / 5) * 32;
        int by = (bi % 5) * 32;
        int tx = tid & 31, ty = tid >> 5;
#pragma unroll
        for (int r = 0; r < 4; r++)
            tile[ty + 8 * r][tx] = W_dec[(by + ty + 8 * r) * HDIM + bx + tx];
        __syncthreads();
#pragma unroll
        for (int r = 0; r < 4; r++)
            g_WdT[(bx + ty + 8 * r) * WIN + by + tx] = tile[tx][ty + 8 * r];
    } else if (blk < 345) {
        __shared__ float red[256];
        int d = blk - 185;
        float a = b_enc[tid] * W_enc[tid * WIN + d]
                + b_enc[tid + 256] * W_enc[(tid + 256) * WIN + d];
        red[tid] = a;
        __syncthreads();
        for (int o = 128; o > 0; o >>= 1) {
            if (tid < o) red[tid] += red[tid + o];
            __syncthreads();
        }
        if (tid == 0) g_v[d] = red[0];
    } else {
        for (int i = tid; i < NTOK; i += 256) g_packed[i] = 0ull;
    }
}

// ---------------- K2: energies, 9 shifts/block, column-split passes ----------
// grid (64, 9) = 576 blocks; launch_bounds(128,5) -> 20 warps/SM (reg cap 102).
// Quadratic form split column-wise into two sequential passes (float4 k=0..10,
// then 11..21) so only 22 packed x pairs are live at a time (44 regs, not 84).
// Exact regrouping: sum_r x_r(h1+h2) -> sum_r x_r h1 + sum_r x_r h2.
#define NS 9
#define CROWS 88
#define CPITCH 92
__global__ __launch_bounds__(128, 5) void energy_kernel(const float* __restrict__ x) {
    __shared__ __align__(16) float Cs[CROWS * CPITCH];
    __shared__ float xs[32 * 81];
    __shared__ float vs[WIN];
    __shared__ float part[4][32];

    int tid = threadIdx.x;
    int lane = tid & 31;
    int w = tid >> 5;
    int tb = blockIdx.x * 32;
    int s0 = blockIdx.y * NS;               // 0,9,...,72
    int qlo = 72 - s0;                      // 72 down to 0

    for (int i = tid; i < CROWS * CPITCH; i += 128) Cs[i] = 0.f;
    __syncthreads();
    for (int i = tid; i < CROWS * CROWS; i += 128) {
        int r = i / CROWS, c = i - r * CROWS;
        Cs[r * CPITCH + 4 + c] = g_C[(qlo + r) * WIN + qlo + c];
    }
    for (int i = tid; i < 32 * IDIM; i += 128) {
        int tok = i / IDIM, ii = i - tok * IDIM;
        xs[tok * 81 + ii] = x[(tb + tok) * IDIM + ii];
    }
    for (int i = tid; i < WIN; i += 128) vs[i] = g_v[i];
    __syncthreads();

    const float* myx = &xs[lane * 81];

    // ---------- phase 1: dual shifts (sA = s0+w, sB = sA+4) ----------
    int qA = qlo + 8 - w;
    int qB = qA - 4;
    int coffB = 4 - w;            // 4,3,2,1
    int p = coffB & 3;            // 0,3,2,1
    int cbo = coffB - p;          // 4,0,0,0  (multiple of 4 -> aligned)

    unsigned long long accA = 0ull, accB = 0ull;
    const float* base = &Cs[coffB * CPITCH + 4 + cbo];

    {   // pass 1: float4 k = 0..10, global pairs 0..21
        unsigned long long xp[22];
#pragma unroll
        for (int j = 0; j < 22; j++) {
            int k0 = 2 * j - p, k1 = 2 * j + 1 - p;
            float lo = (k0 >= 0 && k0 < IDIM) ? myx[k0] : 0.f;
            float hi = (k1 >= 0 && k1 < IDIM) ? myx[k1] : 0.f;
            PACK2(xp[j], lo, hi);
        }
#pragma unroll 1
        for (int r = 0; r < 84; r++) {
            const ulonglong2* cr = reinterpret_cast<const ulonglong2*>(base + r * CPITCH);
            unsigned long long pA0 = 0ull, pA1 = 0ull, pB0 = 0ull, pB1 = 0ull;
#pragma unroll
            for (int k = 0; k < 11; k++) {
                ulonglong2 cv = cr[k];
                FFMA2_ACC(pB0, cv.x, xp[2 * k]);
                FFMA2_ACC(pB1, cv.y, xp[2 * k + 1]);
                if (k >= 1) {
                    FFMA2_ACC(pA0, cv.x, xp[2 * k - 2]);
                    FFMA2_ACC(pA1, cv.y, xp[2 * k - 1]);
                }
            }
            if (r < 80) {
                unsigned long long sm, mp;
                ADD2(sm, pB0, pB1);
                float mv = myx[r];
                PACK2(mp, mv, mv);
                FFMA2_ACC(accB, mp, sm);
            }
            if (r >= 4) {
                unsigned long long sm, mp;
                ADD2(sm, pA0, pA1);
                float mv = myx[r - 4];
                PACK2(mp, mv, mv);
                FFMA2_ACC(accA, mp, sm);
            }
        }
    }
    {   // pass 2: float4 k = 11..21, global pairs 20..41 (local = global-20)
        unsigned long long xp[22];
#pragma unroll
        for (int j = 0; j < 22; j++) {
            int jj = 20 + j;
            int k0 = 2 * jj - p, k1 = 2 * jj + 1 - p;
            float lo = (k0 >= 0 && k0 < IDIM) ? myx[k0] : 0.f;
            float hi = (k1 >= 0 && k1 < IDIM) ? myx[k1] : 0.f;
            PACK2(xp[j], lo, hi);
        }
#pragma unroll 1
        for (int r = 0; r < 84; r++) {
            const ulonglong2* cr = reinterpret_cast<const ulonglong2*>(base + r * CPITCH);
            unsigned long long pA0 = 0ull, pA1 = 0ull, pB0 = 0ull, pB1 = 0ull;
#pragma unroll
            for (int k = 11; k < 22; k++) {
                ulonglong2 cv = cr[k];
                if (k <= 20) {
                    FFMA2_ACC(pB0, cv.x, xp[2 * k - 20]);
                    FFMA2_ACC(pB1, cv.y, xp[2 * k - 19]);
                }
                FFMA2_ACC(pA0, cv.x, xp[2 * k - 22]);
                FFMA2_ACC(pA1, cv.y, xp[2 * k - 21]);
            }
            if (r < 80) {
                unsigned long long sm, mp;
                ADD2(sm, pB0, pB1);
                float mv = myx[r];
                PACK2(mp, mv, mv);
                FFMA2_ACC(accB, mp, sm);
            }
            if (r >= 4) {
                unsigned long long sm, mp;
                ADD2(sm, pA0, pA1);
                float mv = myx[r - 4];
                PACK2(mp, mv, mv);
                FFMA2_ACC(accA, mp, sm);
            }
        }
    }

    float crossA = 0.f, crossB = 0.f;
#pragma unroll 4
    for (int i = 0; i < IDIM; i++) {
        float xv = myx[i];
        crossA += xv * vs[qA + i];
        crossB += xv * vs[qB + i];
    }

    float alo, ahi, blo, bhi;
    UNPACK2(alo, ahi, accA);
    UNPACK2(blo, bhi, accB);
    float EA = (alo + ahi) + 2.f * crossA;
    float EB = (blo + bhi) + 2.f * crossB;

    unsigned ea = __float_as_uint(EA);
    unsigned keyA = ea ^ (unsigned)(((int)ea >> 31) | 0x80000000);
    unsigned eb = __float_as_uint(EB);
    unsigned keyB = eb ^ (unsigned)(((int)eb >> 31) | 0x80000000);
    unsigned long long pkA = ((unsigned long long)keyA << 32) | (unsigned)qA;
    unsigned long long pkB = ((unsigned long long)keyB << 32) | (unsigned)qB;
    unsigned long long best = pkA > pkB ? pkA : pkB;

    // ---------- phase 2: 9th shift (q = qlo, p = 0), 20 rows per warp ----------
    {
        unsigned long long acc = 0ull;
        int r0 = 20 * w;
        {   // pass 1: k = 0..10, pairs 0..21
            unsigned long long xp[22];
#pragma unroll
            for (int j = 0; j < 22; j++) {
                int k0 = 2 * j, k1 = 2 * j + 1;
                float lo = (k0 < IDIM) ? myx[k0] : 0.f;
                float hi = (k1 < IDIM) ? myx[k1] : 0.f;
                PACK2(xp[j], lo, hi);
            }
#pragma unroll 1
            for (int rr = 0; rr < 20; rr++) {
                int r = r0 + rr;
                const ulonglong2* cr = reinterpret_cast<const ulonglong2*>(&Cs[r * CPITCH + 4]);
                unsigned long long p0 = 0ull, p1 = 0ull;
#pragma unroll
                for (int k = 0; k < 11; k++) {
                    ulonglong2 cv = cr[k];
                    FFMA2_ACC(p0, cv.x, xp[2 * k]);
                    FFMA2_ACC(p1, cv.y, xp[2 * k + 1]);
                }
                unsigned long long sm, mp;
                ADD2(sm, p0, p1);
                float mv = myx[r];
                PACK2(mp, mv, mv);
                FFMA2_ACC(acc, mp, sm);
            }
        }
        {   // pass 2: k = 11..20, pairs 22..41 (local = global-22)
            unsigned long long xp[20];
#pragma unroll
            for (int j = 0; j < 20; j++) {
                int jj = 22 + j;
                int k0 = 2 * jj, k1 = 2 * jj + 1;
                float lo = (k0 < IDIM) ? myx[k0] : 0.f;
                float hi = (k1 < IDIM) ? myx[k1] : 0.f;
                PACK2(xp[j], lo, hi);
            }
#pragma unroll 1
            for (int rr = 0; rr < 20; rr++) {
                int r = r0 + rr;
                const ulonglong2* cr = reinterpret_cast<const ulonglong2*>(&Cs[r * CPITCH + 4]);
                unsigned long long p0 = 0ull, p1 = 0ull;
#pragma unroll
                for (int k = 11; k < 21; k++) {
                    ulonglong2 cv = cr[k];
                    FFMA2_ACC(p0, cv.x, xp[2 * k - 22]);
                    FFMA2_ACC(p1, cv.y, xp[2 * k - 21]);
                }
                unsigned long long sm, mp;
                ADD2(sm, p0, p1);
                float mv = myx[r];
                PACK2(mp, mv, mv);
                FFMA2_ACC(acc, mp, sm);
            }
        }
        float plo, phi;
        UNPACK2(plo, phi, acc);
        part[w][lane] = plo + phi;
    }
    __syncthreads();

    if (w == 0) {
        float cross = 0.f;
#pragma unroll 4
        for (int i = 0; i < IDIM; i++) cross += myx[i] * vs[qlo + i];
        float E = ((part[0][lane] + part[1][lane]) + (part[2][lane] + part[3][lane]))
                + 2.f * cross;
        unsigned ebt = __float_as_uint(E);
        unsigned key = ebt ^ (unsigned)(((int)ebt >> 31) | 0x80000000);
        unsigned long long pk = ((unsigned long long)key << 32) | (unsigned)qlo;
        if (pk > best) best = pk;
    }

    if (best) atomicMax(&g_packed[tb + lane], best);
}

// ---------------- K3: h for winning shift, 8 tokens/block, coalesced WeT ----------------
__global__ __launch_bounds__(256) void hcompute_kernel(
    const float* __restrict__ x, const float* __restrict__ b_enc,
    const int* __restrict__ mask_prev)
{
    __shared__ float xsp[TPB][WIN];
    __shared__ int qs[TPB];
    int tid = threadIdx.x;
    int tb = blockIdx.x * TPB;

    if (tid < TPB) qs[tid] = (int)(g_packed[tb + tid] & 0xFFFFFFFFull);
    for (int i = tid; i < TPB * WIN; i += 256) ((float*)xsp)[i] = 0.f;
    __syncthreads();
    for (int idx = tid; idx < TPB * IDIM; idx += 256) {
        int t = idx / IDIM, a = idx - t * IDIM;
        xsp[t][qs[t] + a] = x[(tb + t) * IDIM + a];
    }
    __syncthreads();

    int j0 = 2 * tid;
    float a0[TPB], a1[TPB];
#pragma unroll
    for (int t = 0; t < TPB; t++) { a0[t] = 0.f; a1[t] = 0.f; }

    for (int i = 0; i < WIN; i++) {
        float2 c = *reinterpret_cast<const float2*>(&g_WeT[i * HDIM + j0]);
#pragma unroll
        for (int t = 0; t < TPB; t++) {
            float xv = xsp[t][i];
            a0[t] += xv * c.x;
            a1[t] += xv * c.y;
        }
    }

    float bb0 = b_enc[j0], bb1 = b_enc[j0 + 1];
#pragma unroll
    for (int t = 0; t < TPB; t++) {
        int tg = tb + t;
        int2 m = *reinterpret_cast<const int2*>(&mask_prev[tg * HDIM + j0]);
        float h0 = a0[t] + bb0; if (m.x != 0) h0 = 0.f;
        float h1 = a1[t] + bb1; if (m.y != 0) h1 = 0.f;
        *reinterpret_cast<float2*>(&g_h[tg * HDIM + j0]) = make_float2(h0, h1);
    }
}

// ---------------- K4: exact top-128 via MSD radix select + sparse decoder ----------------
__global__ __launch_bounds__(256) void sortdecode_kernel(
    const float* __restrict__ b_dec, float* __restrict__ out)
{
    __shared__ float hs[HDIM];
    __shared__ int hist[256];
    __shared__ unsigned selbits[16];
    __shared__ unsigned eqbits[16];
    __shared__ int sPrefix, sR, sGt;
    __shared__ float selv[KSEL];
    __shared__ int   selj[KSEL];
    __shared__ float psum[240];

    int t = blockIdx.x;
    int tid = threadIdx.x;
    int q = (int)(g_packed[t] & 0xFFFFFFFFull);

    float h0 = g_h[t * HDIM + tid];
    float h1 = g_h[t * HDIM + tid + 256];
    hs[tid] = h0;
    hs[tid + 256] = h1;
    unsigned v0 = __float_as_uint(h0 * h0);   // >=0 -> bit-monotonic
    unsigned v1 = __float_as_uint(h1 * h1);
    if (tid == 0) { sPrefix = 0; sR = KSEL; sGt = 0; }
    if (tid < 16) { selbits[tid] = 0u; eqbits[tid] = 0u; }
    __syncthreads();

#pragma unroll
    for (int pass = 0; pass < 4; pass++) {
        int shift = 24 - 8 * pass;
        if (tid < 256) hist[tid] = 0;
        __syncthreads();
        int prefix = sPrefix;
        bool act0 = (pass == 0) || ((v0 >> (shift + 8)) == (unsigned)(prefix >> (shift + 8)));
        bool act1 = (pass == 0) || ((v1 >> (shift + 8)) == (unsigned)(prefix >> (shift + 8)));
        if (act0) atomicAdd(&hist[(v0 >> shift) & 255], 1);
        if (act1) atomicAdd(&hist[(v1 >> shift) & 255], 1);
        __syncthreads();
        if (tid < 32) {
            int lane = tid;
            int base = 255 - lane * 8;
            int c[8], lsum = 0;
#pragma unroll
            for (int i = 0; i < 8; i++) { c[i] = hist[base - i]; lsum += c[i]; }
            int xsc = lsum;
#pragma unroll
            for (int o = 1; o < 32; o <<= 1) {
                int y = __shfl_up_sync(0xffffffffu, xsc, o);
                if (lane >= o) xsc += y;
            }
            int pref = xsc - lsum;
            int r = sR;
            if (pref < r && r <= pref + lsum) {
                int run = pref, d = -1, gt_add = 0;
#pragma unroll
                for (int i = 0; i < 8; i++) {
                    if (d < 0 && run + c[i] >= r) { d = base - i; gt_add = run; }
                    run += c[i];
                }
                sPrefix = prefix | (d << shift);
                sR = r - gt_add;
                sGt = sGt + gt_add;
            }
        }
        __syncthreads();
    }

    unsigned Tv = (unsigned)sPrefix;
    int need_eq = KSEL - sGt;

    if (v0 > Tv) atomicOr(&selbits[tid >> 5], 1u << (tid & 31));
    else if (v0 == Tv) atomicOr(&eqbits[tid >> 5], 1u << (tid & 31));
    {
        int j = tid + 256;
        if (v1 > Tv) atomicOr(&selbits[j >> 5], 1u << (j & 31));
        else if (v1 == Tv) atomicOr(&eqbits[j >> 5], 1u << (j & 31));
    }
    __syncthreads();

#pragma unroll
    for (int e = 0; e < 2; e++) {
        int j = tid + 256 * e;
        unsigned vv = (e == 0) ? v0 : v1;
        if (vv == Tv) {
            int w = j >> 5;
            int rk = __popc(eqbits[w] & ((1u << (j & 31)) - 1u));
            for (int u = 0; u < w; u++) rk += __popc(eqbits[u]);
            if (rk < need_eq) atomicOr(&selbits[w], 1u << (j & 31));
        }
    }
    __syncthreads();

#pragma unroll
    for (int e = 0; e < 2; e++) {
        int j = tid + 256 * e;
        int w = j >> 5;
        if (selbits[w] & (1u << (j & 31))) {
            int slot = __popc(selbits[w] & ((1u << (j & 31)) - 1u));
            for (int u = 0; u < w; u++) slot += __popc(selbits[u]);
            selj[slot] = j;
            selv[slot] = hs[j];
        }
    }
    __syncthreads();

    if (tid < 240) {
        int g = tid / IDIM;
        int i = tid - g * IDIM;
        int k0 = (g == 0) ? 0 : (g == 1 ? 43 : 86);
        int k1 = (g == 0) ? 43 : (g == 1 ? 86 : KSEL);
        float a = 0.f;
        for (int k = k0; k < k1; k++)
            a += selv[k] * g_WdT[selj[k] * WIN + q + i];
        psum[tid] = a;
    }
    __syncthreads();
    if (tid < IDIM)
        out[t * IDIM + tid] = psum[tid] + psum[IDIM + tid] + psum[2 * IDIM + tid]
                            + b_dec[q + tid];
}

// ---------------- launch ----------------
extern "C" void kernel_launch(void* const* d_in, const int* in_sizes, int n_in,
                              void* d_out, int out_size) {
    const float* x        = (const float*)d_in[0];
    const float* W_enc    = (const float*)d_in[1];
    const float* b_enc    = (const float*)d_in[2];
    const float* W_dec    = (const float*)d_in[3];
    const float* b_dec    = (const float*)d_in[4];
    const int*   mask_prev= (const int*)d_in[5];
    float* out = (float*)d_out;

    prep_kernel<<<346, 256>>>(W_enc, b_enc, W_dec);
    energy_kernel<<<dim3(64, 9), 128>>>(x);
    hcompute_kernel<<<NTOK / TPB, 256>>>(x, b_enc, mask_prev);
    sortdecode_kernel<<<NTOK, 256>>>(b_dec, out);
}

// round 17
// speedup vs baseline: 1.0531x; 1.0531x over previous
#include <cuda_runtime.h>
#include <cuda_bf16.h>
#include <cstdint>

// Problem constants
#define IDIM   80
#define HDIM   512
#define WIN    160      // IN_EXTRA + IDIM
#define NSHIFT 81       // IN_EXTRA + 1
#define NTOK   2048     // B*T
#define KSEL   128      // 2*CDIM
#define TPB    8        // tokens per hcompute block

// packed f32x2 helpers (Blackwell sm_100a+)
#define FFMA2_ACC(acc, a, b) \
    asm("fma.rn.f32x2 %0, %1, %2, %0;" : "+l"(acc) : "l"(a), "l"(b))
#define ADD2(d, a, b) \
    asm("add.rn.f32x2 %0, %1, %2;" : "=l"(d) : "l"(a), "l"(b))
#define PACK2(d, lo, hi) \
    asm("mov.b64 %0, {%1, %2};" : "=l"(d) : "f"(lo), "f"(hi))
#define UNPACK2(lo, hi, v) \
    asm("mov.b64 {%0, %1}, %2;" : "=f"(lo), "=f"(hi) : "l"(v))

// ---------------- scratch (__device__ globals; no allocation) ----------------
__device__ float g_C[WIN * WIN];            // Gram matrix W_enc^T W_enc (160x160)
__device__ float g_v[WIN];                  // W_enc^T b_enc
__device__ unsigned long long g_packed[NTOK]; // (ordered(E)<<32)|q  via atomicMax
__device__ float g_WeT[WIN * HDIM];         // W_enc transposed
__device__ float g_WdT[HDIM * WIN];         // W_dec transposed
__device__ float g_h[NTOK * HDIM];          // masked h per token

// ---------------- K1: fused prep (gram + transposes + vb + zero) ----------------
__global__ __launch_bounds__(256) void prep_kernel(
    const float* __restrict__ W_enc, const float* __restrict__ b_enc,
    const float* __restrict__ W_dec)
{
    int blk = blockIdx.x;
    int tid = threadIdx.x;

    if (blk < 25) {
        __shared__ float SA[8][32];
        __shared__ float SB[8][32];
        int d0 = (blk % 5) * 32, e0 = (blk / 5) * 32;
        int dd = tid >> 5, ee = tid & 31;
        float a0 = 0.f, a1 = 0.f, a2 = 0.f, a3 = 0.f;
        for (int j0 = 0; j0 < HDIM; j0 += 8) {
            SA[dd][ee] = W_enc[(j0 + dd) * WIN + d0 + ee];
            SB[dd][ee] = W_enc[(j0 + dd) * WIN + e0 + ee];
            __syncthreads();
#pragma unroll
            for (int jj = 0; jj < 8; jj++) {
                float b = SB[jj][ee];
                a0 += SA[jj][dd] * b;
                a1 += SA[jj][dd + 8] * b;
                a2 += SA[jj][dd + 16] * b;
                a3 += SA[jj][dd + 24] * b;
            }
            __syncthreads();
        }
        g_C[(d0 + dd) * WIN + e0 + ee]      = a0;
        g_C[(d0 + dd + 8) * WIN + e0 + ee]  = a1;
        g_C[(d0 + dd + 16) * WIN + e0 + ee] = a2;
        g_C[(d0 + dd + 24) * WIN + e0 + ee] = a3;
    } else if (blk < 105) {
        __shared__ float tile[32][33];
        int bi = blk - 25;
        int bx = (bi % 5) * 32;
        int by = (bi / 5) * 32;
        int tx = tid & 31, ty = tid >> 5;
#pragma unroll
        for (int r = 0; r < 4; r++)
            tile[ty + 8 * r][tx] = W_enc[(by + ty + 8 * r) * WIN + bx + tx];
        __syncthreads();
#pragma unroll
        for (int r = 0; r < 4; r++)
            g_WeT[(bx + ty + 8 * r) * HDIM + by + tx] = tile[tx][ty + 8 * r];
    } else if (blk < 185) {
        __shared__ float tile[32][33];
        int bi = blk - 105;
        int bx = (bi / 5) * 32;
        int by = (bi % 5) * 32;
        int tx = tid & 31, ty = tid >> 5;
#pragma unroll
        for (int r = 0; r < 4; r++)
            tile[ty + 8 * r][tx] = W_dec[(by + ty + 8 * r) * HDIM + bx + tx];
        __syncthreads();
#pragma unroll
        for (int r = 0; r < 4; r++)
            g_WdT[(bx + ty + 8 * r) * WIN + by + tx] = tile[tx][ty + 8 * r];
    } else if (blk < 345) {
        __shared__ float red[256];
        int d = blk - 185;
        float a = b_enc[tid] * W_enc[tid * WIN + d]
                + b_enc[tid + 256] * W_enc[(tid + 256) * WIN + d];
        red[tid] = a;
        __syncthreads();
        for (int o = 128; o > 0; o >>= 1) {
            if (tid < o) red[tid] += red[tid + o];
            __syncthreads();
        }
        if (tid == 0) g_v[d] = red[0];
    } else {
        for (int i = tid; i < NTOK; i += 256) g_packed[i] = 0ull;
    }
}

// ---------------- K2: energies, 9 shifts/block, block-symmetric split ----------
// E = P1(r<40,c<40) + P2(r>=40,c>=40) + 2*P3(r<40,c>=40)  (C symmetric -> exact).
// Masked xp builders make the mid-float4 boundary exact for any alignment p.
// grid (64,9)=576 -> single wave at 4 blocks/SM.
#define NS 9
#define CROWS 88
#define CPITCH 96
__global__ __launch_bounds__(128, 4) void energy_kernel(const float* __restrict__ x) {
    __shared__ __align__(16) float Cs[CROWS * CPITCH];
    __shared__ float xs[32 * 81];
    __shared__ float vs[WIN];
    __shared__ float part[6][32];   // [0..3]=hi-part per warp, [4..5]=lo-part w0,w1

    int tid = threadIdx.x;
    int lane = tid & 31;
    int w = tid >> 5;
    int tb = blockIdx.x * 32;
    int s0 = blockIdx.y * NS;               // 0,9,...,72
    int qlo = 72 - s0;                      // 72 down to 0

    for (int i = tid; i < CROWS * CPITCH; i += 128) Cs[i] = 0.f;
    __syncthreads();
    for (int i = tid; i < CROWS * CROWS; i += 128) {
        int r = i / CROWS, c = i - r * CROWS;
        Cs[r * CPITCH + 4 + c] = g_C[(qlo + r) * WIN + qlo + c];
    }
    for (int i = tid; i < 32 * IDIM; i += 128) {
        int tok = i / IDIM, ii = i - tok * IDIM;
        xs[tok * 81 + ii] = x[(tb + tok) * IDIM + ii];
    }
    for (int i = tid; i < WIN; i += 128) vs[i] = g_v[i];
    __syncthreads();

    const float* myx = &xs[lane * 81];

    // ---------- phase 1: dual shifts (sA = s0+w, sB = sA+4) ----------
    int qA = qlo + 8 - w;
    int qB = qA - 4;
    int coffB = 4 - w;            // 4,3,2,1
    int p = coffB & 3;            // 0,3,2,1
    int cbo = coffB - p;          // 4,0,0,0

    unsigned long long accSA = 0ull, accSB = 0ull;   // symmetric-diag parts (P1+P2)
    unsigned long long accOA = 0ull, accOB = 0ull;   // off-diag part (P3, doubled)
    const float* base = &Cs[coffB * CPITCH + 4 + cbo];

    // ---- P1: rows 0..43, columns x<40 (masked) ----
    {
        unsigned long long xl[22];
#pragma unroll
        for (int j = 0; j < 22; j++) {
            int k0 = 2 * j - p, k1 = 2 * j + 1 - p;
            float lo = (k0 >= 0 && k0 < 40) ? myx[k0] : 0.f;
            float hi = (k1 >= 0 && k1 < 40) ? myx[k1] : 0.f;
            PACK2(xl[j], lo, hi);
        }
#pragma unroll 1
        for (int r = 0; r < 44; r++) {
            const ulonglong2* cr = reinterpret_cast<const ulonglong2*>(base + r * CPITCH);
            unsigned long long pA0 = 0ull, pA1 = 0ull, pB0 = 0ull, pB1 = 0ull;
#pragma unroll
            for (int k = 0; k <= 11; k++) {
                ulonglong2 cv = cr[k];
                if (k <= 10) {
                    FFMA2_ACC(pB0, cv.x, xl[2 * k]);
                    FFMA2_ACC(pB1, cv.y, xl[2 * k + 1]);
                }
                if (k >= 1) {
                    FFMA2_ACC(pA0, cv.x, xl[2 * k - 2]);
                    FFMA2_ACC(pA1, cv.y, xl[2 * k - 1]);
                }
            }
            if (r < 40) {
                unsigned long long sm, mp;
                ADD2(sm, pB0, pB1);
                float mv = myx[r];
                PACK2(mp, mv, mv);
                FFMA2_ACC(accSB, mp, sm);
            }
            if (r >= 4) {
                unsigned long long sm, mp;
                ADD2(sm, pA0, pA1);
                float mv = myx[r - 4];
                PACK2(mp, mv, mv);
                FFMA2_ACC(accSA, mp, sm);
            }
        }
    }
    // ---- P2 (rows 40..83) and P3 (rows 0..43), columns 40<=x<80 (masked) ----
    {
        unsigned long long xh[22];   // pairs 20..41
#pragma unroll
        for (int j = 0; j < 22; j++) {
            int jj = 20 + j;
            int k0 = 2 * jj - p, k1 = 2 * jj + 1 - p;
            float lo = (k0 >= 40 && k0 < IDIM) ? myx[k0] : 0.f;
            float hi = (k1 >= 40 && k1 < IDIM) ? myx[k1] : 0.f;
            PACK2(xh[j], lo, hi);
        }
        // P2
#pragma unroll 1
        for (int r = 40; r < 84; r++) {
            const ulonglong2* cr = reinterpret_cast<const ulonglong2*>(base + r * CPITCH);
            unsigned long long pA0 = 0ull, pA1 = 0ull, pB0 = 0ull, pB1 = 0ull;
#pragma unroll
            for (int k = 10; k <= 21; k++) {
                ulonglong2 cv = cr[k];
                if (k <= 20) {
                    FFMA2_ACC(pB0, cv.x, xh[2 * k - 20]);
                    FFMA2_ACC(pB1, cv.y, xh[2 * k - 19]);
                }
                if (k >= 11) {
                    FFMA2_ACC(pA0, cv.x, xh[2 * k - 22]);
                    FFMA2_ACC(pA1, cv.y, xh[2 * k - 21]);
                }
            }
            if (r < 80) {
                unsigned long long sm, mp;
                ADD2(sm, pB0, pB1);
                float mv = myx[r];
                PACK2(mp, mv, mv);
                FFMA2_ACC(accSB, mp, sm);
            }
            if (r >= 44) {
                unsigned long long sm, mp;
                ADD2(sm, pA0, pA1);
                float mv = myx[r - 4];
                PACK2(mp, mv, mv);
                FFMA2_ACC(accSA, mp, sm);
            }
        }
        // P3
#pragma unroll 1
        for (int r = 0; r < 44; r++) {
            const ulonglong2* cr = reinterpret_cast<const ulonglong2*>(base + r * CPITCH);
            unsigned long long pA0 = 0ull, pA1 = 0ull, pB0 = 0ull, pB1 = 0ull;
#pragma unroll
            for (int k = 10; k <= 21; k++) {
                ulonglong2 cv = cr[k];
                if (k <= 20) {
                    FFMA2_ACC(pB0, cv.x, xh[2 * k - 20]);
                    FFMA2_ACC(pB1, cv.y, xh[2 * k - 19]);
                }
                if (k >= 11) {
                    FFMA2_ACC(pA0, cv.x, xh[2 * k - 22]);
                    FFMA2_ACC(pA1, cv.y, xh[2 * k - 21]);
                }
            }
            if (r < 40) {
                unsigned long long sm, mp;
                ADD2(sm, pB0, pB1);
                float mv = myx[r];
                PACK2(mp, mv, mv);
                FFMA2_ACC(accOB, mp, sm);
            }
            if (r >= 4) {
                unsigned long long sm, mp;
                ADD2(sm, pA0, pA1);
                float mv = myx[r - 4];
                PACK2(mp, mv, mv);
                FFMA2_ACC(accOA, mp, sm);
            }
        }
    }

    float crossA = 0.f, crossB = 0.f;
#pragma unroll 4
    for (int i = 0; i < IDIM; i++) {
        float xv = myx[i];
        crossA += xv * vs[qA + i];
        crossB += xv * vs[qB + i];
    }

    float salo, sahi, sblo, sbhi, oalo, oahi, oblo, obhi;
    UNPACK2(salo, sahi, accSA);
    UNPACK2(sblo, sbhi, accSB);
    UNPACK2(oalo, oahi, accOA);
    UNPACK2(oblo, obhi, accOB);
    float EA = (salo + sahi) + 2.f * (oalo + oahi) + 2.f * crossA;
    float EB = (sblo + sbhi) + 2.f * (oblo + obhi) + 2.f * crossB;

    unsigned ea = __float_as_uint(EA);
    unsigned keyA = ea ^ (unsigned)(((int)ea >> 31) | 0x80000000);
    unsigned eb = __float_as_uint(EB);
    unsigned keyB = eb ^ (unsigned)(((int)eb >> 31) | 0x80000000);
    unsigned long long pkA = ((unsigned long long)keyA << 32) | (unsigned)qA;
    unsigned long long pkB = ((unsigned long long)keyB << 32) | (unsigned)qB;
    unsigned long long best = pkA > pkB ? pkA : pkB;

    // ---------- phase 2: 9th shift (q = qlo, p = 0, aligned blocks) ----------
    // w0/w1: rows 0..39 -> lo cols (P1) + hi cols (P3, doubled).
    // w2/w3: rows 40..79 -> hi cols only (P2).
    {
        unsigned long long xq[20];
        int r0 = 20 * w;
        if (w < 2) {
#pragma unroll
            for (int j = 0; j < 20; j++)
                PACK2(xq[j], myx[2 * j], myx[2 * j + 1]);
            unsigned long long accd = 0ull;
#pragma unroll 1
            for (int rr = 0; rr < 20; rr++) {
                int r = r0 + rr;
                const ulonglong2* cr = reinterpret_cast<const ulonglong2*>(&Cs[r * CPITCH + 4]);
                unsigned long long p0 = 0ull, p1 = 0ull;
#pragma unroll
                for (int k = 0; k < 10; k++) {
                    ulonglong2 cv = cr[k];
                    FFMA2_ACC(p0, cv.x, xq[2 * k]);
                    FFMA2_ACC(p1, cv.y, xq[2 * k + 1]);
                }
                unsigned long long sm, mp;
                ADD2(sm, p0, p1);
                float mv = myx[r];
                PACK2(mp, mv, mv);
                FFMA2_ACC(accd, mp, sm);
            }
            float dlo, dhi;
            UNPACK2(dlo, dhi, accd);
            part[4 + w][lane] = dlo + dhi;
        }
#pragma unroll
        for (int j = 0; j < 20; j++)
            PACK2(xq[j], myx[40 + 2 * j], myx[40 + 2 * j + 1]);
        unsigned long long acco = 0ull;
#pragma unroll 1
        for (int rr = 0; rr < 20; rr++) {
            int r = r0 + rr;
            const ulonglong2* cr = reinterpret_cast<const ulonglong2*>(&Cs[r * CPITCH + 4]);
            unsigned long long p0 = 0ull, p1 = 0ull;
#pragma unroll
            for (int k = 10; k < 20; k++) {
                ulonglong2 cv = cr[k];
                FFMA2_ACC(p0, cv.x, xq[2 * k - 20]);
                FFMA2_ACC(p1, cv.y, xq[2 * k - 19]);
            }
            unsigned long long sm, mp;
            ADD2(sm, p0, p1);
            float mv = myx[r];
            PACK2(mp, mv, mv);
            FFMA2_ACC(acco, mp, sm);
        }
        float olo, ohi;
        UNPACK2(olo, ohi, acco);
        part[w][lane] = olo + ohi;
    }
    __syncthreads();

    if (w == 0) {
        float cross = 0.f;
#pragma unroll 4
        for (int i = 0; i < IDIM; i++) cross += myx[i] * vs[qlo + i];
        float E = (part[4][lane] + part[5][lane])                 // P1
                + (part[2][lane] + part[3][lane])                 // P2
                + 2.f * (part[0][lane] + part[1][lane])           // P3
                + 2.f * cross;
        unsigned ebt = __float_as_uint(E);
        unsigned key = ebt ^ (unsigned)(((int)ebt >> 31) | 0x80000000);
        unsigned long long pk = ((unsigned long long)key << 32) | (unsigned)qlo;
        if (pk > best) best = pk;
    }

    if (best) atomicMax(&g_packed[tb + lane], best);
}

// ---------------- K3: h for winning shift, 8 tokens/block, coalesced WeT ----------------
__global__ __launch_bounds__(256) void hcompute_kernel(
    const float* __restrict__ x, const float* __restrict__ b_enc,
    const int* __restrict__ mask_prev)
{
    __shared__ float xsp[TPB][WIN];
    __shared__ int qs[TPB];
    int tid = threadIdx.x;
    int tb = blockIdx.x * TPB;

    if (tid < TPB) qs[tid] = (int)(g_packed[tb + tid] & 0xFFFFFFFFull);
    for (int i = tid; i < TPB * WIN; i += 256) ((float*)xsp)[i] = 0.f;
    __syncthreads();
    for (int idx = tid; idx < TPB * IDIM; idx += 256) {
        int t = idx / IDIM, a = idx - t * IDIM;
        xsp[t][qs[t] + a] = x[(tb + t) * IDIM + a];
    }
    __syncthreads();

    int j0 = 2 * tid;
    float a0[TPB], a1[TPB];
#pragma unroll
    for (int t = 0; t < TPB; t++) { a0[t] = 0.f; a1[t] = 0.f; }

    for (int i = 0; i < WIN; i++) {
        float2 c = *reinterpret_cast<const float2*>(&g_WeT[i * HDIM + j0]);
#pragma unroll
        for (int t = 0; t < TPB; t++) {
            float xv = xsp[t][i];
            a0[t] += xv * c.x;
            a1[t] += xv * c.y;
        }
    }

    float bb0 = b_enc[j0], bb1 = b_enc[j0 + 1];
#pragma unroll
    for (int t = 0; t < TPB; t++) {
        int tg = tb + t;
        int2 m = *reinterpret_cast<const int2*>(&mask_prev[tg * HDIM + j0]);
        float h0 = a0[t] + bb0; if (m.x != 0) h0 = 0.f;
        float h1 = a1[t] + bb1; if (m.y != 0) h1 = 0.f;
        *reinterpret_cast<float2*>(&g_h[tg * HDIM + j0]) = make_float2(h0, h1);
    }
}

// ---------------- K4: exact top-128 via MSD radix select + sparse decoder ----------------
__global__ __launch_bounds__(256) void sortdecode_kernel(
    const float* __restrict__ b_dec, float* __restrict__ out)
{
    __shared__ float hs[HDIM];
    __shared__ int hist[256];
    __shared__ unsigned selbits[16];
    __shared__ unsigned eqbits[16];
    __shared__ int sPrefix, sR, sGt;
    __shared__ float selv[KSEL];
    __shared__ int   selj[KSEL];
    __shared__ float psum[240];

    int t = blockIdx.x;
    int tid = threadIdx.x;
    int q = (int)(g_packed[t] & 0xFFFFFFFFull);

    float h0 = g_h[t * HDIM + tid];
    float h1 = g_h[t * HDIM + tid + 256];
    hs[tid] = h0;
    hs[tid + 256] = h1;
    unsigned v0 = __float_as_uint(h0 * h0);   // >=0 -> bit-monotonic
    unsigned v1 = __float_as_uint(h1 * h1);
    if (tid == 0) { sPrefix = 0; sR = KSEL; sGt = 0; }
    if (tid < 16) { selbits[tid] = 0u; eqbits[tid] = 0u; }
    __syncthreads();

#pragma unroll
    for (int pass = 0; pass < 4; pass++) {
        int shift = 24 - 8 * pass;
        if (tid < 256) hist[tid] = 0;
        __syncthreads();
        int prefix = sPrefix;
        bool act0 = (pass == 0) || ((v0 >> (shift + 8)) == (unsigned)(prefix >> (shift + 8)));
        bool act1 = (pass == 0) || ((v1 >> (shift + 8)) == (unsigned)(prefix >> (shift + 8)));
        if (act0) atomicAdd(&hist[(v0 >> shift) & 255], 1);
        if (act1) atomicAdd(&hist[(v1 >> shift) & 255], 1);
        __syncthreads();
        if (tid < 32) {
            int lane = tid;
            int base = 255 - lane * 8;
            int c[8], lsum = 0;
#pragma unroll
            for (int i = 0; i < 8; i++) { c[i] = hist[base - i]; lsum += c[i]; }
            int xsc = lsum;
#pragma unroll
            for (int o = 1; o < 32; o <<= 1) {
                int y = __shfl_up_sync(0xffffffffu, xsc, o);
                if (lane >= o) xsc += y;
            }
            int pref = xsc - lsum;
            int r = sR;
            if (pref < r && r <= pref + lsum) {
                int run = pref, d = -1, gt_add = 0;
#pragma unroll
                for (int i = 0; i < 8; i++) {
                    if (d < 0 && run + c[i] >= r) { d = base - i; gt_add = run; }
                    run += c[i];
                }
                sPrefix = prefix | (d << shift);
                sR = r - gt_add;
                sGt = sGt + gt_add;
            }
        }
        __syncthreads();
    }

    unsigned Tv = (unsigned)sPrefix;
    int need_eq = KSEL - sGt;

    if (v0 > Tv) atomicOr(&selbits[tid >> 5], 1u << (tid & 31));
    else if (v0 == Tv) atomicOr(&eqbits[tid >> 5], 1u << (tid & 31));
    {
        int j = tid + 256;
        if (v1 > Tv) atomicOr(&selbits[j >> 5], 1u << (j & 31));
        else if (v1 == Tv) atomicOr(&eqbits[j >> 5], 1u << (j & 31));
    }
    __syncthreads();

#pragma unroll
    for (int e = 0; e < 2; e++) {
        int j = tid + 256 * e;
        unsigned vv = (e == 0) ? v0 : v1;
        if (vv == Tv) {
            int w = j >> 5;
            int rk = __popc(eqbits[w] & ((1u << (j & 31)) - 1u));
            for (int u = 0; u < w; u++) rk += __popc(eqbits[u]);
            if (rk < need_eq) atomicOr(&selbits[w], 1u << (j & 31));
        }
    }
    __syncthreads();

#pragma unroll
    for (int e = 0; e < 2; e++) {
        int j = tid + 256 * e;
        int w = j >> 5;
        if (selbits[w] & (1u << (j & 31))) {
            int slot = __popc(selbits[w] & ((1u << (j & 31)) - 1u));
            for (int u = 0; u < w; u++) slot += __popc(selbits[u]);
            selj[slot] = j;
            selv[slot] = hs[j];
        }
    }
    __syncthreads();

    if (tid < 240) {
        int g = tid / IDIM;
        int i = tid - g * IDIM;
        int k0 = (g == 0) ? 0 : (g == 1 ? 43 : 86);
        int k1 = (g == 0) ? 43 : (g == 1 ? 86 : KSEL);
        float a = 0.f;
        for (int k = k0; k < k1; k++)
            a += selv[k] * g_WdT[selj[k] * WIN + q + i];
        psum[tid] = a;
    }
    __syncthreads();
    if (tid < IDIM)
        out[t * IDIM + tid] = psum[tid] + psum[IDIM + tid] + psum[2 * IDIM + tid]
                            + b_dec[q + tid];
}

// ---------------- launch ----------------
extern "C" void kernel_launch(void* const* d_in, const int* in_sizes, int n_in,
                              void* d_out, int out_size) {
    const float* x        = (const float*)d_in[0];
    const float* W_enc    = (const float*)d_in[1];
    const float* b_enc    = (const float*)d_in[2];
    const float* W_dec    = (const float*)d_in[3];
    const float* b_dec    = (const float*)d_in[4];
    const int*   mask_prev= (const int*)d_in[5];
    float* out = (float*)d_out;

    prep_kernel<<<346, 256>>>(W_enc, b_enc, W_dec);
    energy_kernel<<<dim3(64, 9), 128>>>(x);
    hcompute_kernel<<<NTOK / TPB, 256>>>(x, b_enc, mask_prev);
    sortdecode_kernel<<<NTOK, 256>>>(b_dec, out);
}